// round 1
// baseline (speedup 1.0000x reference)
#include <cuda_runtime.h>
#include <math.h>

#ifndef M_PI
#define M_PI 3.14159265358979323846
#endif

// Slice-half tile: 130 rows x 267 floats (row stride 267 ==> 11 mod 32 banks).
// Row 0 is a zero guard; rows 1..129 hold volume rows; col 0 and cols 257,258
// are zero guard columns so xi in [-1,256] needs no weight masking.
#define TS    267
#define TROWS 130
#define TILE_BYTES (TROWS * TS * 4)

__global__ void fp_zero_kernel(float4* __restrict__ out, int n4) {
    int i = blockIdx.x * blockDim.x + threadIdx.x;
    if (i < n4) out[i] = make_float4(0.f, 0.f, 0.f, 0.f);
}

extern __shared__ float tile[];

__global__ void __launch_bounds__(1024, 1)
fp_main_kernel(const float* __restrict__ vol, float* __restrict__ out)
{
    const int bx  = blockIdx.x;
    const int z   = bx >> 2;          // 0..255 slice
    const int p   = (bx >> 1) & 1;    // phase: row half (0: yi in [-1,127], 1: yi in [128,255])
    const int vg  = bx & 1;           // view group of 8
    const int tid = threadIdx.x;

    __shared__ float s_cos[16], s_sin[16];
    if (tid < 16) {
        // Reproduce reference float32 angle arithmetic, then accurate cos/sin.
        float unit = (float)(M_PI / 16.0);
        float mu   = (float)(M_PI / 180.0);
        float a = __fadd_rn(mu, __fmul_rn((float)tid, unit));
        double da = (double)a;
        s_cos[tid] = (float)cos(da);
        s_sin[tid] = (float)sin(da);
    }

    // ---- zero guards ----
    for (int i = tid; i < TS; i += 1024) tile[i] = 0.f;                    // srow 0 guard
    if (p) for (int i = tid; i < TS; i += 1024) tile[129 * TS + i] = 0.f;  // srow 129 guard (phase 1 only)
    for (int i = tid; i < TROWS; i += 1024) {
        tile[i * TS + 0]   = 0.f;
        tile[i * TS + 257] = 0.f;
        tile[i * TS + 258] = 0.f;
    }

    // ---- load slice half (rows [128p, 128p + nrows)) into srow 1.. ----
    const int nrows = 129 - p;  // phase 0: rows 0..128 (129); phase 1: rows 128..255 (128)
    const float4* __restrict__ vsrc =
        (const float4*)(vol + ((size_t)z << 16) + (p ? (128 * 256) : 0));
    for (int i = tid; i < nrows * 64; i += 1024) {
        int r = i >> 6, c4 = i & 63;
        float4 v = vsrc[i];
        float* dst = &tile[(r + 1) * TS + 1 + (c4 << 2)];
        dst[0] = v.x; dst[1] = v.y; dst[2] = v.z; dst[3] = v.w;
    }
    __syncthreads();

    const int warp = tid >> 5, lane = tid & 31;
    // srow = floor(iy) mapped into tile coords for this phase
    const int      rowMagic = p ? 0x4B40007F : 0x4B3FFFFF; // bits(12582912+k) - magic = srow
    const int      rowLo    = p;            // valid srow range [rowLo, 128]
    const unsigned rowSpan  = 128u - (unsigned)p;
    const float    ylo = p ? 128.f : -1.f;
    const float    yhi = p ? 256.f : 128.f;

    // 8 views x 256 y-lines per CTA; one warp per line, lanes along x.
    for (int line = warp; line < 2048; line += 32) {
        const int v = (line >> 8) + (vg << 3);
        const int y = line & 255;
        const float c = s_cos[v], s = s_sin[v];   // s > 0 for all views
        const float yf = (float)y - 127.5f;
        // ix = c*x + A ; iy = s*x + B
        const float A = fmaf(-s, yf, fmaf(-c, 127.5f, 127.5f));
        const float B = fmaf( c, yf, fmaf(-s, 127.5f, 127.5f));

        // x-range where iy lands in this phase AND ix in [-1,257) (conservative +-1 margin)
        const float inv_s = __fdividef(1.f, s);
        const float inv_c = __fdividef(1.f, c);
        float xl = (ylo - B) * inv_s;
        float xh = (yhi - B) * inv_s;
        float e0 = (-1.f  - A) * inv_c;
        float e1 = (257.f - A) * inv_c;
        xl = fmaxf(xl, fminf(e0, e1));
        xh = fminf(xh, fmaxf(e0, e1));
        int xlo = max(0,   (int)floorf(xl) - 1);
        int xhi = min(256, (int)ceilf(xh) + 1);
        if (xlo >= xhi) continue;

        float ix = fmaf(c, (float)(xlo + lane), A);
        float iy = fmaf(s, (float)(xlo + lane), B);
        const float dix = c * 32.f, diy = s * 32.f;
        float acc = 0.f;

        for (int xb = xlo; xb < xhi; xb += 32) {
            // floor via round-to-nearest magic on (t - 0.5); half-integer ties give
            // wx==1.0 on the lower corner which is bilinear-identical to floor.
            float mx = (ix - 0.5f) + 12582912.f;
            float my = (iy - 0.5f) + 12582912.f;
            int scol = __float_as_int(mx) - 0x4B3FFFFF;   // = floor(ix) + 1
            int srow = __float_as_int(my) - rowMagic;
            float wx = ix - (mx - 12582912.f);
            float wy = iy - (my - 12582912.f);

            bool ok = ((unsigned)scol <= 257u) &&
                      ((unsigned)(srow - rowLo) <= rowSpan) &&
                      ((xb + lane) < xhi);

            unsigned sc_ = min((unsigned)scol, 257u);
            unsigned sr_ = min((unsigned)srow, 128u);
            const float* tp = tile + sr_ * TS + sc_;
            float v00 = tp[0], v01 = tp[1], v10 = tp[TS], v11 = tp[TS + 1];
            float h0  = fmaf(wx, v01 - v00, v00);
            float h1  = fmaf(wx, v11 - v10, v10);
            float val = fmaf(wy, h1 - h0, h0);
            acc += ok ? val : 0.f;

            ix += dix; iy += diy;
        }

        #pragma unroll
        for (int o = 16; o; o >>= 1) acc += __shfl_xor_sync(0xffffffffu, acc, o);
        if (lane == 0) atomicAdd(&out[(((z << 8) + y) << 4) + v], acc);
    }
}

extern "C" void kernel_launch(void* const* d_in, const int* in_sizes, int n_in,
                              void* d_out, int out_size) {
    (void)in_sizes; (void)n_in;
    cudaFuncSetAttribute(fp_main_kernel,
                         cudaFuncAttributeMaxDynamicSharedMemorySize, TILE_BYTES);
    fp_zero_kernel<<<512, 512>>>((float4*)d_out, out_size / 4);
    fp_main_kernel<<<1024, 1024, TILE_BYTES>>>((const float*)d_in[0], (float*)d_out);
}